// round 16
// baseline (speedup 1.0000x reference)
#include <cuda_runtime.h>
#include <cstdint>

// out[b, 0:128]   = x[b, :]                       for b < B
// out[b, 128:256] = sum_{e: dst[e]==b} x[src[e]]
//
// Pipeline (2 graph nodes):
//   K1 bin:  ELL binning; PDL trigger at end.
//   K2 fused, ROLE-SPLIT BY BLOCK with differential sync:
//       blocks [0, COPY_BLOCKS): copy out[b,0:128]=x[b]; depend only on x,
//           so they SKIP cudaGridDependencySynchronize and stream
//           immediately — true concurrency with bin's tail / the gather
//           blocks' sync-wait.
//       blocks [COPY_BLOCKS, ..): cudaGridDependencySynchronize, then the
//           untouchable gather body (any store BEFORE the loop destroys
//           ptxas load batching — measured 3x). Trailing self-cleans.

#define NFEAT   128
#define ROW_OUT 256
#define MAX_E   640000
#define B_MAX   65536
#define SLOTS   32
#define COPY_BLOCKS 800

__device__ int  g_cnt[B_MAX];
__device__ int  g_ell[B_MAX * SLOTS];
__device__ int2 g_ovf[MAX_E];
__device__ int  g_ovf_count;

__global__ void bin_kernel(const int* __restrict__ ei, int E, int B) {
    int i = blockIdx.x * blockDim.x + threadIdx.x;
    if (i < E) {
        int d = __ldg(ei + E + i);
        if ((unsigned)d < (unsigned)B) {
            int s = __ldg(ei + i);
            int k = atomicAdd(&g_cnt[d], 1);
            if (k < SLOTS) {
                g_ell[d * SLOTS + k] = s;
            } else {
                int p = atomicAdd(&g_ovf_count, 1);
                g_ovf[p] = make_int2(s, d);
            }
        }
    }
    cudaTriggerProgrammaticLaunchCompletion();
}

__global__ void main_kernel(const float* __restrict__ x,
                            float* __restrict__ out,
                            int B) {
    if ((int)blockIdx.x < COPY_BLOCKS) {
        // ---- Copy role: no dependency on bin -> NO grid sync. Streams
        //      while the gather blocks below wait for bin to complete. ----
        int i = blockIdx.x * blockDim.x + threadIdx.x;
        int nthreads = COPY_BLOCKS * blockDim.x;
        int nq = B * (NFEAT / 4);
        for (int q = i; q < nq; q += nthreads) {
            int row = q >> 5;            // 32 float4s per x row
            int c4  = q & 31;
            float4 v = __ldg(reinterpret_cast<const float4*>(
                                 x + (size_t)row * NFEAT) + c4);
            reinterpret_cast<float4*>(out + (size_t)row * ROW_OUT)[c4] = v;
        }
        return;
    }

    // ---- Gather role: needs bin's output. ----
    cudaGridDependencySynchronize();

    int warp = (((int)blockIdx.x - COPY_BLOCKS) * blockDim.x
                + threadIdx.x) >> 5;
    int lane = threadIdx.x & 31;
    if (warp >= B) return;
    int b = warp;

    int c_raw = g_cnt[b];
    int c = c_raw < SLOTS ? c_raw : SLOTS;

    // Coalesced preload of this row's source list (one slot per lane).
    int src_l = (lane < c) ? g_ell[b * SLOTS + lane] : 0;

    float4 acc = make_float4(0.f, 0.f, 0.f, 0.f);
    for (int k = 0; k < c; k++) {
        int se = __shfl_sync(0xFFFFFFFFu, src_l, k);
        float4 v = __ldg(reinterpret_cast<const float4*>(
                             x + (size_t)se * NFEAT) + lane);
        acc.x += v.x; acc.y += v.y; acc.z += v.z; acc.w += v.w;
    }

    // Rare path: degree exceeded SLOTS -> extras live in the overflow list.
    if (c_raw > SLOTS) {
        int n = g_ovf_count;
        for (int e = 0; e < n; e++) {
            int2 ed = g_ovf[e];
            if (ed.y == b) {
                float4 v = __ldg(reinterpret_cast<const float4*>(
                                     x + (size_t)ed.x * NFEAT) + lane);
                acc.x += v.x; acc.y += v.y; acc.z += v.z; acc.w += v.w;
            }
        }
    }

    // Second half only (first half written by the copy-role blocks).
    float4* orow = reinterpret_cast<float4*>(out + (size_t)b * ROW_OUT);
    orow[(NFEAT / 4) + lane] = acc;

    // Trailing self-clean (measured benign): restores counters for the
    // next graph replay; no memset nodes needed.
    if (lane == 0) g_cnt[b] = 0;
    if (b == 0 && lane == 0) g_ovf_count = 0;
}

extern "C" void kernel_launch(void* const* d_in, const int* in_sizes, int n_in,
                              void* d_out, int out_size) {
    const float* x        = (const float*)d_in[0];
    const int*   edge_idx = (const int*)d_in[1];
    float*       out      = (float*)d_out;

    int B = out_size / ROW_OUT;          // 50000
    int E = in_sizes[1] / 2;             // 640000

    {   // K1: binning
        int threads = 256;
        int blocks = (E + threads - 1) / threads;
        bin_kernel<<<blocks, threads>>>(edge_idx, E, B);
    }
    {   // K2: copy blocks (no sync) + gather blocks (sync), PDL-launched
        int threads = 256;                          // 8 warps/block
        int gather_blocks = (B + 7) / 8;            // 6250
        int blocks = COPY_BLOCKS + gather_blocks;

        cudaLaunchConfig_t cfg = {};
        cfg.gridDim  = dim3(blocks, 1, 1);
        cfg.blockDim = dim3(threads, 1, 1);
        cfg.stream = 0;
        cudaLaunchAttribute attrs[1];
        attrs[0].id = cudaLaunchAttributeProgrammaticStreamSerialization;
        attrs[0].val.programmaticStreamSerializationAllowed = 1;
        cfg.attrs = attrs;
        cfg.numAttrs = 1;
        cudaLaunchKernelEx(&cfg, main_kernel, x, out, B);
    }
}

// round 17
// speedup vs baseline: 1.0077x; 1.0077x over previous
#include <cuda_runtime.h>
#include <cstdint>

// out[b, 0:128]   = x[b, :]                       for b < B
// out[b, 128:256] = sum_{e: dst[e]==b} x[src[e]]
//
// Pipeline (2 graph nodes):
//   K1 SINGLE-WAVE role-split (1184 blocks = 148 SMs x 8 blocks):
//       blocks [0, BIN_BLOCKS):   grid-stride edge binning (latency-idle
//                                 atomic chains).
//       blocks [BIN_BLOCKS, ..):  grid-stride copy out[b,0:128]=x[b] with
//                                 4x-batched loads.
//       One wave => both roles are resident SIMULTANEOUSLY (R14/R16 failed
//       because copy blocks landed in later waves / after bin's trigger).
//   K2 main: PDL-dependent gather-only body (measured best, 23.7us —
//       untouchable loop: any store BEFORE it destroys ptxas load
//       batching). Trailing self-cleans replace all memsets.

#define NFEAT   128
#define ROW_OUT 256
#define MAX_E   640000
#define B_MAX   65536
#define SLOTS   32
#define WAVE_BLOCKS 1184
#define BIN_BLOCKS  600

__device__ int  g_cnt[B_MAX];
__device__ int  g_ell[B_MAX * SLOTS];
__device__ int2 g_ovf[MAX_E];
__device__ int  g_ovf_count;

__global__ __launch_bounds__(256)
void bin_copy_kernel(const int* __restrict__ ei,
                     const float* __restrict__ x,
                     float* __restrict__ out,
                     int E, int B) {
    int tid = threadIdx.x;

    if ((int)blockIdx.x < BIN_BLOCKS) {
        // ---- Bin role: grid-stride over edges ----
        int stride = BIN_BLOCKS * blockDim.x;
        for (int i = blockIdx.x * blockDim.x + tid; i < E; i += stride) {
            int d = __ldg(ei + E + i);
            if ((unsigned)d < (unsigned)B) {
                int s = __ldg(ei + i);
                int k = atomicAdd(&g_cnt[d], 1);
                if (k < SLOTS) {
                    g_ell[d * SLOTS + k] = s;
                } else {
                    int p = atomicAdd(&g_ovf_count, 1);
                    g_ovf[p] = make_int2(s, d);
                }
            }
        }
    } else {
        // ---- Copy role: grid-stride over B*32 float4s, 4x batched ----
        int cb = blockIdx.x - BIN_BLOCKS;
        int S  = (WAVE_BLOCKS - BIN_BLOCKS) * blockDim.x;
        int nq = B * (NFEAT / 4);
        int q  = cb * blockDim.x + tid;
        for (; q + 3 * S < nq; q += 4 * S) {
            int q0 = q, q1 = q + S, q2 = q + 2 * S, q3 = q + 3 * S;
            // Batch all 4 loads before any store (MLP 4).
            float4 v0 = __ldg(reinterpret_cast<const float4*>(
                                  x + (size_t)(q0 >> 5) * NFEAT) + (q0 & 31));
            float4 v1 = __ldg(reinterpret_cast<const float4*>(
                                  x + (size_t)(q1 >> 5) * NFEAT) + (q1 & 31));
            float4 v2 = __ldg(reinterpret_cast<const float4*>(
                                  x + (size_t)(q2 >> 5) * NFEAT) + (q2 & 31));
            float4 v3 = __ldg(reinterpret_cast<const float4*>(
                                  x + (size_t)(q3 >> 5) * NFEAT) + (q3 & 31));
            reinterpret_cast<float4*>(out + (size_t)(q0 >> 5) * ROW_OUT)[q0 & 31] = v0;
            reinterpret_cast<float4*>(out + (size_t)(q1 >> 5) * ROW_OUT)[q1 & 31] = v1;
            reinterpret_cast<float4*>(out + (size_t)(q2 >> 5) * ROW_OUT)[q2 & 31] = v2;
            reinterpret_cast<float4*>(out + (size_t)(q3 >> 5) * ROW_OUT)[q3 & 31] = v3;
        }
        for (; q < nq; q += S) {
            float4 v = __ldg(reinterpret_cast<const float4*>(
                                 x + (size_t)(q >> 5) * NFEAT) + (q & 31));
            reinterpret_cast<float4*>(out + (size_t)(q >> 5) * ROW_OUT)[q & 31] = v;
        }
    }

    cudaTriggerProgrammaticLaunchCompletion();
}

__global__ void main_kernel(const float* __restrict__ x,
                            float* __restrict__ out,
                            int B) {
    cudaGridDependencySynchronize();

    int warp = (blockIdx.x * blockDim.x + threadIdx.x) >> 5;
    int lane = threadIdx.x & 31;
    if (warp >= B) return;
    int b = warp;

    int c_raw = g_cnt[b];
    int c = c_raw < SLOTS ? c_raw : SLOTS;

    // Coalesced preload of this row's source list (one slot per lane).
    int src_l = (lane < c) ? g_ell[b * SLOTS + lane] : 0;

    float4 acc = make_float4(0.f, 0.f, 0.f, 0.f);
    for (int k = 0; k < c; k++) {
        int se = __shfl_sync(0xFFFFFFFFu, src_l, k);
        float4 v = __ldg(reinterpret_cast<const float4*>(
                             x + (size_t)se * NFEAT) + lane);
        acc.x += v.x; acc.y += v.y; acc.z += v.z; acc.w += v.w;
    }

    // Rare path: degree exceeded SLOTS -> extras live in the overflow list.
    if (c_raw > SLOTS) {
        int n = g_ovf_count;
        for (int e = 0; e < n; e++) {
            int2 ed = g_ovf[e];
            if (ed.y == b) {
                float4 v = __ldg(reinterpret_cast<const float4*>(
                                     x + (size_t)ed.x * NFEAT) + lane);
                acc.x += v.x; acc.y += v.y; acc.z += v.z; acc.w += v.w;
            }
        }
    }

    // Second half only (first half written by K1's copy-role blocks).
    float4* orow = reinterpret_cast<float4*>(out + (size_t)b * ROW_OUT);
    orow[(NFEAT / 4) + lane] = acc;

    // Trailing self-clean (measured benign): restores counters for the
    // next graph replay; no memset nodes needed.
    if (lane == 0) g_cnt[b] = 0;
    if (b == 0 && lane == 0) g_ovf_count = 0;
}

extern "C" void kernel_launch(void* const* d_in, const int* in_sizes, int n_in,
                              void* d_out, int out_size) {
    const float* x        = (const float*)d_in[0];
    const int*   edge_idx = (const int*)d_in[1];
    float*       out      = (float*)d_out;

    int B = out_size / ROW_OUT;          // 50000
    int E = in_sizes[1] / 2;             // 640000

    {   // K1: single-wave bin+copy (both roles resident together)
        bin_copy_kernel<<<WAVE_BLOCKS, 256>>>(edge_idx, x, out, E, B);
    }
    {   // K2: gather-only main, PDL-overlapped ramp
        int threads = 256;                          // 8 warps/block
        int blocks = (B + 7) / 8;
        cudaLaunchConfig_t cfg = {};
        cfg.gridDim  = dim3(blocks, 1, 1);
        cfg.blockDim = dim3(threads, 1, 1);
        cfg.stream = 0;
        cudaLaunchAttribute attrs[1];
        attrs[0].id = cudaLaunchAttributeProgrammaticStreamSerialization;
        attrs[0].val.programmaticStreamSerializationAllowed = 1;
        cfg.attrs = attrs;
        cfg.numAttrs = 1;
        cudaLaunchKernelEx(&cfg, main_kernel, x, out, B);
    }
}